// round 9
// baseline (speedup 1.0000x reference)
#include <cuda_runtime.h>
#include <math.h>

#define BINS 50
#define MBINS (BINS * BINS)                  // 2500
#define JBINS (BINS * BINS * BINS * BINS)    // 6,250,000

// ---------------- device scratch (no allocations allowed) ----------------
// All state restored to these initial values by the end of every launch.
__device__ double   g_sums[14] = {};
__device__ double   g_entJ = 0.0;
__device__ unsigned g_minq = 0xFFFFFFFFu, g_maxq = 0u;
__device__ unsigned g_minr = 0xFFFFFFFFu, g_maxr = 0u;
__device__ unsigned g_mins = 0xFFFFFFFFu, g_maxs = 0u;
__device__ unsigned g_bar = 0;             // grid-barrier counter
__device__ unsigned g_done = 0;            // last-block detector
__device__ unsigned g_hist_joint[JBINS];   // 25 MB, starts zero, kept zero
__device__ unsigned g_hist_q[MBINS];
__device__ unsigned g_hist_r[MBINS];

// ---------------- helpers ----------------
__device__ __forceinline__ unsigned fenc(float f) {
    unsigned u = __float_as_uint(f);
    return (u & 0x80000000u) ? ~u : (u | 0x80000000u);
}
__device__ __forceinline__ float fdec(unsigned e) {
    unsigned u = (e & 0x80000000u) ? (e & 0x7fffffffu) : ~e;
    return __uint_as_float(u);
}
__device__ __forceinline__ int binof(float x, float lo, float scale) {
    int i = (int)floorf((x - lo) * scale);
    i = i < 0 ? 0 : i;
    return i > (BINS - 1) ? (BINS - 1) : i;
}

// counter-based grid barrier; grid sized so ALL blocks are co-resident.
__device__ __forceinline__ void grid_barrier(unsigned target) {
    __syncthreads();
    if (threadIdx.x == 0) {
        __threadfence();
        atomicAdd(&g_bar, 1u);
        while (*(volatile unsigned*)&g_bar < target) {}
        __threadfence();
    }
    __syncthreads();
}

// compact cholesky params: 0..9 = l00,l10,l11,l20,l21,l22,l30,l31,l32,l33 ; 10..13 = mean
__device__ void chol_from_sums(float* out, double nn) {
    double shs[14];
#pragma unroll
    for (int k = 0; k < 14; k++) shs[k] = g_sums[k];
    double mean[4];
#pragma unroll
    for (int i = 0; i < 4; i++) mean[i] = shs[i] / nn;
    float cov[4][4];
    int ix = 4;
#pragma unroll
    for (int i = 0; i < 4; i++)
#pragma unroll
        for (int j = i; j < 4; j++) {
            float c = (float)((shs[ix++] - nn * mean[i] * mean[j]) / (nn - 1.0));
            cov[i][j] = c; cov[j][i] = c;
        }
#pragma unroll
    for (int i = 0; i < 4; i++) cov[i][i] += 1e-6f;
    float L[4][4] = {};
#pragma unroll
    for (int j = 0; j < 4; j++) {
        float d = cov[j][j];
#pragma unroll
        for (int k = 0; k < 4; k++) if (k < j) d -= L[j][k] * L[j][k];
        float dj = sqrtf(d);
        L[j][j] = dj;
        float inv = __frcp_rn(dj);
#pragma unroll
        for (int i = 0; i < 4; i++) if (i > j) {
            float v = cov[i][j];
#pragma unroll
            for (int k = 0; k < 4; k++) if (k < j) v -= L[i][k] * L[j][k];
            L[i][j] = v * inv;
        }
    }
    out[0] = L[0][0];
    out[1] = L[1][0]; out[2] = L[1][1];
    out[3] = L[2][0]; out[4] = L[2][1]; out[5] = L[2][2];
    out[6] = L[3][0]; out[7] = L[3][1]; out[8] = L[3][2]; out[9] = L[3][3];
#pragma unroll
    for (int i = 0; i < 4; i++) out[10 + i] = (float)mean[i];
}

__device__ __forceinline__ void xform(float4 zv, const float* p,
                                      float& s0, float& s1, float& s2, float& s3) {
    s0 = fmaf(zv.x, p[0], p[10]);
    s1 = fmaf(zv.y, p[2], fmaf(zv.x, p[1], p[11]));
    s2 = fmaf(zv.z, p[5], fmaf(zv.y, p[4], fmaf(zv.x, p[3], p[12])));
    s3 = fmaf(zv.w, p[9], fmaf(zv.z, p[8], fmaf(zv.y, p[7], fmaf(zv.x, p[6], p[13]))));
}

__device__ __forceinline__ double qsum(uint4 v) {
    float a = v.x ? (float)v.x * __logf((float)v.x) : 0.0f;
    float b = v.y ? (float)v.y * __logf((float)v.y) : 0.0f;
    float c = v.z ? (float)v.z * __logf((float)v.z) : 0.0f;
    float d = v.w ? (float)v.w * __logf((float)v.w) : 0.0f;
    return ((double)a + (double)b) + ((double)c + (double)d);
}

// ---------------- kernel 1: moments + min/max of q and r (R2 body) ----------------
__global__ void __launch_bounds__(256) k_stats(const float2* __restrict__ q,
                                               const float2* __restrict__ r, int n) {
    int idx = blockIdx.x * blockDim.x + threadIdx.x;
    int stride = gridDim.x * blockDim.x;
    double s[14];
#pragma unroll
    for (int k = 0; k < 14; k++) s[k] = 0.0;
    unsigned mnq = 0xFFFFFFFFu, mxq = 0u, mnr = 0xFFFFFFFFu, mxr = 0u;

    for (int i = idx; i < n; i += stride) {
        float2 qv = q[i];
        float2 rv = r[i];
        double x0 = qv.x, x1 = qv.y, x2 = rv.x, x3 = rv.y;
        s[0] += x0; s[1] += x1; s[2] += x2; s[3] += x3;
        s[4]  += x0 * x0; s[5]  += x0 * x1; s[6]  += x0 * x2; s[7]  += x0 * x3;
        s[8]  += x1 * x1; s[9]  += x1 * x2; s[10] += x1 * x3;
        s[11] += x2 * x2; s[12] += x2 * x3; s[13] += x3 * x3;
        unsigned e;
        e = fenc(qv.x); mnq = min(mnq, e); mxq = max(mxq, e);
        e = fenc(qv.y); mnq = min(mnq, e); mxq = max(mxq, e);
        e = fenc(rv.x); mnr = min(mnr, e); mxr = max(mxr, e);
        e = fenc(rv.y); mnr = min(mnr, e); mxr = max(mxr, e);
    }
    const unsigned FULL = 0xFFFFFFFFu;
#pragma unroll
    for (int k = 0; k < 14; k++)
        for (int off = 16; off; off >>= 1) s[k] += __shfl_down_sync(FULL, s[k], off);
    for (int off = 16; off; off >>= 1) {
        mnq = min(mnq, __shfl_down_sync(FULL, mnq, off));
        mxq = max(mxq, __shfl_down_sync(FULL, mxq, off));
        mnr = min(mnr, __shfl_down_sync(FULL, mnr, off));
        mxr = max(mxr, __shfl_down_sync(FULL, mxr, off));
    }
    __shared__ double   sh[8][14];
    __shared__ unsigned shm[8][4];
    int wid = threadIdx.x >> 5, lane = threadIdx.x & 31;
    if (lane == 0) {
#pragma unroll
        for (int k = 0; k < 14; k++) sh[wid][k] = s[k];
        shm[wid][0] = mnq; shm[wid][1] = mxq; shm[wid][2] = mnr; shm[wid][3] = mxr;
    }
    __syncthreads();
    if (threadIdx.x == 0) {
        int nw = blockDim.x >> 5;
        for (int w = 1; w < nw; w++) {
#pragma unroll
            for (int k = 0; k < 14; k++) sh[0][k] += sh[w][k];
            shm[0][0] = min(shm[0][0], shm[w][0]);
            shm[0][1] = max(shm[0][1], shm[w][1]);
            shm[0][2] = min(shm[0][2], shm[w][2]);
            shm[0][3] = max(shm[0][3], shm[w][3]);
        }
#pragma unroll
        for (int k = 0; k < 14; k++) atomicAdd(&g_sums[k], sh[0][k]);
        atomicMin(&g_minq, shm[0][0]); atomicMax(&g_maxq, shm[0][1]);
        atomicMin(&g_minr, shm[0][2]); atomicMax(&g_maxr, shm[0][3]);
    }
}

// ---------------- kernel 2: marginal histograms (R2 body) ----------------
__global__ void __launch_bounds__(256) k_margHist(const float2* __restrict__ q,
                                                  const float2* __restrict__ r, int n) {
    __shared__ unsigned shq[MBINS];
    __shared__ unsigned shr[MBINS];
    for (int i = threadIdx.x; i < MBINS; i += blockDim.x) { shq[i] = 0u; shr[i] = 0u; }
    __syncthreads();

    float loq = fdec(g_minq), hiq = fdec(g_maxq);
    float lor = fdec(g_minr), hir = fdec(g_maxr);
    float sq = (float)BINS / (hiq - loq);
    float sr = (float)BINS / (hir - lor);

    int idx = blockIdx.x * blockDim.x + threadIdx.x;
    int stride = gridDim.x * blockDim.x;
    for (int i = idx; i < n; i += stride) {
        float2 qv = q[i];
        atomicAdd(&shq[binof(qv.x, loq, sq) * BINS + binof(qv.y, loq, sq)], 1u);
        float2 rv = r[i];
        atomicAdd(&shr[binof(rv.x, lor, sr) * BINS + binof(rv.y, lor, sr)], 1u);
    }
    __syncthreads();
    for (int i = threadIdx.x; i < MBINS; i += blockDim.x) {
        unsigned a = shq[i]; if (a) atomicAdd(&g_hist_q[i], a);
        unsigned b = shr[i]; if (b) atomicAdd(&g_hist_r[i], b);
    }
}

// ---------------- kernel 3: fused cholesky + tmm + jhist + entJ + final ----------------
// All blocks co-resident (grid sized by occupancy query) -> grid barriers safe.
__global__ void __launch_bounds__(256)
k_zwork(const float4* __restrict__ z, float* __restrict__ out,
        int n, int S, int nblk) {
    __shared__ float sP[14];
    __shared__ double shd[8][2];
    __shared__ unsigned shmn[8], shmx[8];
    __shared__ int s_last;

    const int tid = threadIdx.x;
    const int wid = tid >> 5, lane = tid & 31;
    const int gid = blockIdx.x * 256 + tid;
    const int gstride = nblk * 256;
    const unsigned FULL = 0xFFFFFFFFu;

    if (tid == 0) chol_from_sums(sP, (double)n);
    __syncthreads();
    float P[14];
#pragma unroll
    for (int i = 0; i < 14; i++) P[i] = sP[i];

    // ---- phase 1: transform + global min/max of samples ----
    {
        unsigned mn = 0xFFFFFFFFu, mx = 0u;
        for (int i = gid; i < S; i += gstride) {
            float s0, s1, s2, s3;
            xform(z[i], P, s0, s1, s2, s3);
            unsigned e;
            e = fenc(s0); mn = min(mn, e); mx = max(mx, e);
            e = fenc(s1); mn = min(mn, e); mx = max(mx, e);
            e = fenc(s2); mn = min(mn, e); mx = max(mx, e);
            e = fenc(s3); mn = min(mn, e); mx = max(mx, e);
        }
        for (int off = 16; off; off >>= 1) {
            mn = min(mn, __shfl_down_sync(FULL, mn, off));
            mx = max(mx, __shfl_down_sync(FULL, mx, off));
        }
        if (lane == 0) { shmn[wid] = mn; shmx[wid] = mx; }
        __syncthreads();
        if (tid == 0) {
            for (int w = 1; w < 8; w++) { mn = min(mn, shmn[w]); mx = max(mx, shmx[w]); }
            atomicMin(&g_mins, mn);
            atomicMax(&g_maxs, mx);
        }
    }

    grid_barrier(nblk);

    // ---- phase 2: joint histogram ----
    {
        float lo = fdec(g_mins), hi = fdec(g_maxs);
        float sc = (float)BINS / (hi - lo);
        for (int i = gid; i < S; i += gstride) {
            float s0, s1, s2, s3;
            xform(z[i], P, s0, s1, s2, s3);
            int flat = ((binof(s0, lo, sc) * BINS + binof(s1, lo, sc)) * BINS +
                        binof(s2, lo, sc)) * BINS + binof(s3, lo, sc);
            atomicAdd(&g_hist_joint[flat], 1u);
        }
    }

    grid_barrier(2 * nblk);

    // ---- phase 3: entropy scan + clear-on-read ----
    {
        double a0 = 0.0, a1 = 0.0, a2 = 0.0, a3 = 0.0;
        uint4* p = (uint4*)g_hist_joint;
        const uint4 zero = make_uint4(0u, 0u, 0u, 0u);
        const int Q = JBINS / 4;
        int i = gid;
        for (; i + 3 * gstride < Q; i += 4 * gstride) {
            uint4 a = p[i];
            uint4 b = p[i + gstride];
            uint4 c = p[i + 2 * gstride];
            uint4 d = p[i + 3 * gstride];
            if (a.x | a.y | a.z | a.w) { a0 += qsum(a); p[i] = zero; }
            if (b.x | b.y | b.z | b.w) { a1 += qsum(b); p[i + gstride] = zero; }
            if (c.x | c.y | c.z | c.w) { a2 += qsum(c); p[i + 2 * gstride] = zero; }
            if (d.x | d.y | d.z | d.w) { a3 += qsum(d); p[i + 3 * gstride] = zero; }
        }
        for (; i < Q; i += gstride) {
            uint4 v = p[i];
            if (v.x | v.y | v.z | v.w) { a0 += qsum(v); p[i] = zero; }
        }
        double sum = (a0 + a1) + (a2 + a3);
        for (int off = 16; off; off >>= 1) sum += __shfl_down_sync(FULL, sum, off);
        if (lane == 0) shd[wid][0] = sum;
        __syncthreads();
        if (tid == 0) {
            for (int w = 1; w < 8; w++) sum += shd[w][0];
            atomicAdd(&g_entJ, sum);
            __threadfence();
            unsigned t = atomicAdd(&g_done, 1u);
            s_last = (t == (unsigned)nblk - 1u) ? 1 : 0;
        }
        __syncthreads();
    }
    if (!s_last) return;

    // ---- last block: marginal entropies + final scalar + full state reset ----
    __threadfence();
    {
        double sq = 0.0, sr = 0.0;
        for (int k = tid; k < MBINS; k += 256) {
            unsigned a = g_hist_q[k]; if (a) { sq += (double)a * (double)logf((float)a); g_hist_q[k] = 0u; }
            unsigned b = g_hist_r[k]; if (b) { sr += (double)b * (double)logf((float)b); g_hist_r[k] = 0u; }
        }
        for (int off = 16; off; off >>= 1) {
            sq += __shfl_down_sync(FULL, sq, off);
            sr += __shfl_down_sync(FULL, sr, off);
        }
        if (lane == 0) { shd[wid][0] = sq; shd[wid][1] = sr; }
        __syncthreads();
        if (tid == 0) {
            for (int w = 1; w < 8; w++) { sq += shd[w][0]; sr += shd[w][1]; }
            double nn = (double)n, SS = (double)S;
            double H_T = log(nn) - sq / nn;
            double H_I = log(nn) - sr / nn;
            double H_J = log(SS) - g_entJ / SS;
            double v = H_J / (H_T + H_I);
            v = v < 0.0 ? 0.0 : (v > 1.0 ? 1.0 : v);
            out[0] = (float)v;

            g_entJ = 0.0;
#pragma unroll
            for (int k = 0; k < 14; k++) g_sums[k] = 0.0;
            g_minq = 0xFFFFFFFFu; g_maxq = 0u;
            g_minr = 0xFFFFFFFFu; g_maxr = 0u;
            g_mins = 0xFFFFFFFFu; g_maxs = 0u;
            g_bar = 0u;
            g_done = 0u;
        }
    }
}

// ---------------- launch ----------------
extern "C" void kernel_launch(void* const* d_in, const int* in_sizes, int n_in,
                              void* d_out, int out_size) {
    const float2* q = (const float2*)d_in[0];
    const float2* r = (const float2*)d_in[1];
    const float4* z = (const float4*)d_in[2];
    int n = in_sizes[0] / 2;   // 200000 rows of D=2
    int S = in_sizes[2] / 4;   // 2000000 rows of 2D=4

    // size the fused grid so every block is co-resident (computed every call;
    // pure host queries — capture-legal, deterministic)
    int perSM = 0, nsm = 0;
    cudaOccupancyMaxActiveBlocksPerMultiprocessor(&perSM, k_zwork, 256, 0);
    cudaDeviceGetAttribute(&nsm, cudaDevAttrMultiProcessorCount, 0);
    if (perSM < 1) perSM = 1;
    int nblk = perSM * nsm;

    k_stats<<<296, 256>>>(q, r, n);
    k_margHist<<<64, 256>>>(q, r, n);
    k_zwork<<<nblk, 256>>>(z, (float*)d_out, n, S, nblk);
}

// round 10
// speedup vs baseline: 1.3568x; 1.3568x over previous
#include <cuda_runtime.h>
#include <math.h>

#define BINS 50
#define MBINS (BINS * BINS)                  // 2500
#define JBINS (BINS * BINS * BINS * BINS)    // 6,250,000

// ---------------- device scratch (no allocations allowed) ----------------
// All state is restored to these initial values at the end of every
// kernel_launch execution (clear-on-read), so each graph replay is identical.
__device__ double   g_sums[14] = {};   // 0..3 sum x_i ; 4..13 upper-tri sum x_i x_j
__device__ double   g_entJ = 0.0;      // sum c*log(c) over joint hist
__device__ unsigned g_minq = 0xFFFFFFFFu, g_maxq = 0u;
__device__ unsigned g_minr = 0xFFFFFFFFu, g_maxr = 0u;
__device__ unsigned g_mins = 0xFFFFFFFFu, g_maxs = 0u;
__device__ float    g_L[16];           // lower-tri cholesky factor (row major)
__device__ float    g_mean[4];
__device__ unsigned g_hist_joint[JBINS];   // 25 MB, starts zero, kept zero
__device__ unsigned g_hist_q[MBINS];
__device__ unsigned g_hist_r[MBINS];

// ---------------- helpers ----------------
__device__ __forceinline__ unsigned fenc(float f) {
    unsigned u = __float_as_uint(f);
    return (u & 0x80000000u) ? ~u : (u | 0x80000000u);
}
__device__ __forceinline__ float fdec(unsigned e) {
    unsigned u = (e & 0x80000000u) ? (e & 0x7fffffffu) : ~e;
    return __uint_as_float(u);
}
__device__ __forceinline__ int binof(float x, float lo, float scale) {
    int i = (int)floorf((x - lo) * scale);
    i = i < 0 ? 0 : i;
    return i > (BINS - 1) ? (BINS - 1) : i;
}

// ---------------- kernel 1: moments + min/max (fp32 accum, fp64 combine) ----------------
__global__ void __launch_bounds__(256) k_stats(const float2* __restrict__ q,
                                               const float2* __restrict__ r, int n) {
    int idx = blockIdx.x * blockDim.x + threadIdx.x;
    int stride = gridDim.x * blockDim.x;
    float s[14];
#pragma unroll
    for (int k = 0; k < 14; k++) s[k] = 0.0f;
    unsigned mnq = 0xFFFFFFFFu, mxq = 0u, mnr = 0xFFFFFFFFu, mxr = 0u;

    for (int i = idx; i < n; i += stride) {
        float2 qv = q[i];
        float2 rv = r[i];
        float x0 = qv.x, x1 = qv.y, x2 = rv.x, x3 = rv.y;
        s[0] += x0; s[1] += x1; s[2] += x2; s[3] += x3;
        s[4]  = fmaf(x0, x0, s[4]);  s[5]  = fmaf(x0, x1, s[5]);
        s[6]  = fmaf(x0, x2, s[6]);  s[7]  = fmaf(x0, x3, s[7]);
        s[8]  = fmaf(x1, x1, s[8]);  s[9]  = fmaf(x1, x2, s[9]);
        s[10] = fmaf(x1, x3, s[10]); s[11] = fmaf(x2, x2, s[11]);
        s[12] = fmaf(x2, x3, s[12]); s[13] = fmaf(x3, x3, s[13]);
        unsigned e;
        e = fenc(x0); mnq = min(mnq, e); mxq = max(mxq, e);
        e = fenc(x1); mnq = min(mnq, e); mxq = max(mxq, e);
        e = fenc(x2); mnr = min(mnr, e); mxr = max(mxr, e);
        e = fenc(x3); mnr = min(mnr, e); mxr = max(mxr, e);
    }

    const unsigned FULL = 0xFFFFFFFFu;
    // fp32 warp reduction — 14 independent shuffle chains, 4-byte each
#pragma unroll
    for (int off = 16; off; off >>= 1) {
#pragma unroll
        for (int k = 0; k < 14; k++) s[k] += __shfl_down_sync(FULL, s[k], off);
        mnq = min(mnq, __shfl_down_sync(FULL, mnq, off));
        mxq = max(mxq, __shfl_down_sync(FULL, mxq, off));
        mnr = min(mnr, __shfl_down_sync(FULL, mnr, off));
        mxr = max(mxr, __shfl_down_sync(FULL, mxr, off));
    }

    __shared__ double   sh[8][14];
    __shared__ unsigned shm[8][4];
    int wid = threadIdx.x >> 5, lane = threadIdx.x & 31;
    if (lane == 0) {
#pragma unroll
        for (int k = 0; k < 14; k++) sh[wid][k] = (double)s[k];
        shm[wid][0] = mnq; shm[wid][1] = mxq; shm[wid][2] = mnr; shm[wid][3] = mxr;
    }
    __syncthreads();
    // cross-warp combine in fp64; lanes 0..13 each own one accumulator
    if (threadIdx.x < 14) {
        int k = threadIdx.x;
        double acc = sh[0][k];
#pragma unroll
        for (int w = 1; w < 8; w++) acc += sh[w][k];
        atomicAdd(&g_sums[k], acc);
    } else if (threadIdx.x == 32) {
        unsigned a = shm[0][0], b = shm[0][1], c = shm[0][2], d = shm[0][3];
#pragma unroll
        for (int w = 1; w < 8; w++) {
            a = min(a, shm[w][0]); b = max(b, shm[w][1]);
            c = min(c, shm[w][2]); d = max(d, shm[w][3]);
        }
        atomicMin(&g_minq, a); atomicMax(&g_maxq, b);
        atomicMin(&g_minr, c); atomicMax(&g_maxr, d);
    }
}

// ---------------- kernel 2: mean, covariance (+eps*I), fp32 cholesky ----------------
__global__ void k_finalize(int n) {
    __shared__ double shs[14];
    int t = threadIdx.x;
    if (t < 14) shs[t] = g_sums[t];
    __syncthreads();
    if (t != 0) return;

    double nn = (double)n;
    double mean[4];
#pragma unroll
    for (int i = 0; i < 4; i++) mean[i] = shs[i] / nn;
    float cov[4][4];
    int idx = 4;
#pragma unroll
    for (int i = 0; i < 4; i++)
#pragma unroll
        for (int j = i; j < 4; j++) {
            float c = (float)((shs[idx++] - nn * mean[i] * mean[j]) / (nn - 1.0));
            cov[i][j] = c; cov[j][i] = c;
        }
#pragma unroll
    for (int i = 0; i < 4; i++) cov[i][i] += 1e-6f;

    float L[4][4] = {};
#pragma unroll
    for (int j = 0; j < 4; j++) {
        float d = cov[j][j];
#pragma unroll
        for (int k = 0; k < 4; k++) if (k < j) d -= L[j][k] * L[j][k];
        float dj = sqrtf(d);
        L[j][j] = dj;
        float inv = __frcp_rn(dj);
#pragma unroll
        for (int i = 0; i < 4; i++) if (i > j) {
            float v = cov[i][j];
#pragma unroll
            for (int k = 0; k < 4; k++) if (k < j) v -= L[i][k] * L[j][k];
            L[i][j] = v * inv;
        }
    }
#pragma unroll
    for (int i = 0; i < 4; i++) {
        g_mean[i] = (float)mean[i];
#pragma unroll
        for (int j = 0; j < 4; j++) g_L[i * 4 + j] = L[i][j];
    }
}

// ---------------- kernel 3: marginal histograms (shared-memory privatized) ----------------
__global__ void __launch_bounds__(256) k_margHist(const float2* __restrict__ q,
                                                  const float2* __restrict__ r, int n) {
    __shared__ unsigned shq[MBINS];
    __shared__ unsigned shr[MBINS];
    for (int i = threadIdx.x; i < MBINS; i += blockDim.x) { shq[i] = 0u; shr[i] = 0u; }
    __syncthreads();

    float loq = fdec(g_minq), hiq = fdec(g_maxq);
    float lor = fdec(g_minr), hir = fdec(g_maxr);
    float sq = (float)BINS / (hiq - loq);
    float sr = (float)BINS / (hir - lor);

    int idx = blockIdx.x * blockDim.x + threadIdx.x;
    int stride = gridDim.x * blockDim.x;
    for (int i = idx; i < n; i += stride) {
        float2 qv = q[i];
        atomicAdd(&shq[binof(qv.x, loq, sq) * BINS + binof(qv.y, loq, sq)], 1u);
        float2 rv = r[i];
        atomicAdd(&shr[binof(rv.x, lor, sr) * BINS + binof(rv.y, lor, sr)], 1u);
    }
    __syncthreads();
    for (int i = threadIdx.x; i < MBINS; i += blockDim.x) {
        unsigned a = shq[i]; if (a) atomicAdd(&g_hist_q[i], a);
        unsigned b = shr[i]; if (b) atomicAdd(&g_hist_r[i], b);
    }
}

__device__ __forceinline__ void transform_row(float4 zv, const float* L, const float* m,
                                              float& s0, float& s1, float& s2, float& s3) {
    s0 = fmaf(zv.x, L[0], m[0]);
    s1 = fmaf(zv.y, L[5],  fmaf(zv.x, L[4],  m[1]));
    s2 = fmaf(zv.z, L[10], fmaf(zv.y, L[9],  fmaf(zv.x, L[8],  m[2])));
    s3 = fmaf(zv.w, L[15], fmaf(zv.z, L[14], fmaf(zv.y, L[13], fmaf(zv.x, L[12], m[3]))));
}

// ---------------- kernel 4: transform + global min/max of samples ----------------
__global__ void __launch_bounds__(256) k_tmm(const float4* __restrict__ z, int S) {
    float L[16], m[4];
#pragma unroll
    for (int i = 0; i < 16; i++) L[i] = g_L[i];
#pragma unroll
    for (int i = 0; i < 4; i++) m[i] = g_mean[i];

    unsigned mn = 0xFFFFFFFFu, mx = 0u;
    int idx = blockIdx.x * blockDim.x + threadIdx.x;
    int stride = gridDim.x * blockDim.x;
    for (int i = idx; i < S; i += stride) {
        float s0, s1, s2, s3;
        transform_row(z[i], L, m, s0, s1, s2, s3);
        unsigned e;
        e = fenc(s0); mn = min(mn, e); mx = max(mx, e);
        e = fenc(s1); mn = min(mn, e); mx = max(mx, e);
        e = fenc(s2); mn = min(mn, e); mx = max(mx, e);
        e = fenc(s3); mn = min(mn, e); mx = max(mx, e);
    }
    const unsigned FULL = 0xFFFFFFFFu;
    for (int off = 16; off; off >>= 1) {
        mn = min(mn, __shfl_down_sync(FULL, mn, off));
        mx = max(mx, __shfl_down_sync(FULL, mx, off));
    }
    __shared__ unsigned shmn[8], shmx[8];
    int wid = threadIdx.x >> 5, lane = threadIdx.x & 31;
    if (lane == 0) { shmn[wid] = mn; shmx[wid] = mx; }
    __syncthreads();
    if (threadIdx.x == 0) {
        int nw = blockDim.x >> 5;
        for (int w = 1; w < nw; w++) { mn = min(mn, shmn[w]); mx = max(mx, shmx[w]); }
        atomicMin(&g_mins, mn);
        atomicMax(&g_maxs, mx);
    }
}

// ---------------- kernel 5: joint histogram ----------------
__global__ void __launch_bounds__(256) k_jhist(const float4* __restrict__ z, int S) {
    float L[16], m[4];
#pragma unroll
    for (int i = 0; i < 16; i++) L[i] = g_L[i];
#pragma unroll
    for (int i = 0; i < 4; i++) m[i] = g_mean[i];
    float lo = fdec(g_mins), hi = fdec(g_maxs);
    float sc = (float)BINS / (hi - lo);

    int idx = blockIdx.x * blockDim.x + threadIdx.x;
    int stride = gridDim.x * blockDim.x;
    for (int i = idx; i < S; i += stride) {
        float s0, s1, s2, s3;
        transform_row(z[i], L, m, s0, s1, s2, s3);
        int i0 = binof(s0, lo, sc);
        int i1 = binof(s1, lo, sc);
        int i2 = binof(s2, lo, sc);
        int i3 = binof(s3, lo, sc);
        int flat = ((i0 * BINS + i1) * BINS + i2) * BINS + i3;
        atomicAdd(&g_hist_joint[flat], 1u);
    }
}

// ---------------- kernel 6: entropy over joint hist, clear-on-read ----------------
__global__ void __launch_bounds__(256) k_entJ() {
    double sum = 0.0;
    uint4* p = (uint4*)g_hist_joint;
    const uint4 zero = make_uint4(0u, 0u, 0u, 0u);
    int idx = blockIdx.x * blockDim.x + threadIdx.x;
    int stride = gridDim.x * blockDim.x;
    for (int i = idx; i < JBINS / 4; i += stride) {
        uint4 v = p[i];
        if (v.x | v.y | v.z | v.w) {
            if (v.x) sum += (double)v.x * (double)logf((float)v.x);
            if (v.y) sum += (double)v.y * (double)logf((float)v.y);
            if (v.z) sum += (double)v.z * (double)logf((float)v.z);
            if (v.w) sum += (double)v.w * (double)logf((float)v.w);
            p[i] = zero;
        }
    }
    const unsigned FULL = 0xFFFFFFFFu;
    for (int off = 16; off; off >>= 1) sum += __shfl_down_sync(FULL, sum, off);
    __shared__ double sh[8];
    int wid = threadIdx.x >> 5, lane = threadIdx.x & 31;
    if (lane == 0) sh[wid] = sum;
    __syncthreads();
    if (threadIdx.x == 0) {
        int nw = blockDim.x >> 5;
        for (int w = 1; w < nw; w++) sum += sh[w];
        atomicAdd(&g_entJ, sum);
    }
}

// ---------------- kernel 7: marginal entropies + final scalar + state reset ----------------
__global__ void __launch_bounds__(512) k_final(float* out, int n, int S) {
    double sq = 0.0, sr = 0.0;
    for (int i = threadIdx.x; i < MBINS; i += blockDim.x) {
        unsigned a = g_hist_q[i]; if (a) { sq += (double)a * (double)logf((float)a); g_hist_q[i] = 0u; }
        unsigned b = g_hist_r[i]; if (b) { sr += (double)b * (double)logf((float)b); g_hist_r[i] = 0u; }
    }
    const unsigned FULL = 0xFFFFFFFFu;
    for (int off = 16; off; off >>= 1) {
        sq += __shfl_down_sync(FULL, sq, off);
        sr += __shfl_down_sync(FULL, sr, off);
    }
    __shared__ double shq[16], shr[16];
    int wid = threadIdx.x >> 5, lane = threadIdx.x & 31;
    if (lane == 0) { shq[wid] = sq; shr[wid] = sr; }
    __syncthreads();
    if (threadIdx.x == 0) {
        int nw = blockDim.x >> 5;
        for (int w = 1; w < nw; w++) { sq += shq[w]; sr += shr[w]; }
        double nn = (double)n, SS = (double)S;
        double H_T = log(nn) - sq / nn;
        double H_I = log(nn) - sr / nn;
        double H_J = log(SS) - g_entJ / SS;
        double v = H_J / (H_T + H_I);
        v = v < 0.0 ? 0.0 : (v > 1.0 ? 1.0 : v);
        out[0] = (float)v;

        // restore scalar state for the next replay
        g_entJ = 0.0;
#pragma unroll
        for (int k = 0; k < 14; k++) g_sums[k] = 0.0;
        g_minq = 0xFFFFFFFFu; g_maxq = 0u;
        g_minr = 0xFFFFFFFFu; g_maxr = 0u;
        g_mins = 0xFFFFFFFFu; g_maxs = 0u;
    }
}

// ---------------- launch ----------------
extern "C" void kernel_launch(void* const* d_in, const int* in_sizes, int n_in,
                              void* d_out, int out_size) {
    const float* q = (const float*)d_in[0];
    const float* r = (const float*)d_in[1];
    const float* z = (const float*)d_in[2];
    int n = in_sizes[0] / 2;   // 200000 rows of D=2
    int S = in_sizes[2] / 4;   // 2000000 rows of 2D=4

    k_stats<<<592, 256>>>((const float2*)q, (const float2*)r, n);
    k_finalize<<<1, 32>>>(n);
    k_margHist<<<64, 256>>>((const float2*)q, (const float2*)r, n);
    k_tmm<<<1184, 256>>>((const float4*)z, S);
    k_jhist<<<1184, 256>>>((const float4*)z, S);
    k_entJ<<<1184, 256>>>();
    k_final<<<1, 512>>>((float*)d_out, n, S);
}